// round 10
// baseline (speedup 1.0000x reference)
#include <cuda_runtime.h>
#include <math.h>

#define NN 50000
#define EE 800000
#define D  64

// ---------------- scratch (device globals; no allocations allowed) ----------
__device__ float g_q[NN * D];
__device__ float g_k[NN * D];
__device__ float g_v[NN * D];
__device__ float g_ep[(size_t)EE * D];   // 204.8 MB
__device__ float g_nn[NN * D];
__device__ int   g_hist[NN];
__device__ int   g_off[NN + 1];
__device__ int   g_cur[NN];
__device__ int   g_perm[EE];

// ---------------- kernels ---------------------------------------------------

__global__ void k_zero_hist() {
    int i = blockIdx.x * blockDim.x + threadIdx.x;
    if (i < NN) g_hist[i] = 0;
}

// q,k,v projections fused: one X-tile load, three weights. 32 rows per block.
__global__ __launch_bounds__(256) void k_qkv(
    const float* __restrict__ X,
    const float* __restrict__ Wq, const float* __restrict__ Wk,
    const float* __restrict__ Wv)
{
    __shared__ float Ws[D * D];
    __shared__ float Xs[32][D];
    int t = threadIdx.x;
    int row0 = blockIdx.x * 32;
    for (int i = t; i < 32 * D; i += 256) {
        int r = i >> 6, c = i & 63;
        int gr = row0 + r;
        Xs[r][c] = (gr < NN) ? X[gr * D + c] : 0.f;
    }
    const float* Wlist[3] = {Wq, Wk, Wv};
    float2* Olist[3] = {(float2*)g_q, (float2*)g_k, (float2*)g_v};
    int l = t & 31, ng = t >> 5;
    for (int m = 0; m < 3; m++) {
        __syncthreads();
        for (int i = t; i < D * D; i += 256) Ws[i] = Wlist[m][i];
        __syncthreads();
        const float2* Ws2 = (const float2*)Ws;
        float2* Y2 = Olist[m];
#pragma unroll
        for (int rr = 0; rr < 4; rr++) {
            int r = rr * 8 + ng;
            int gr = row0 + r;
            float a0 = 0.f, a1 = 0.f;
#pragma unroll
            for (int i = 0; i < D; i++) {
                float x = Xs[r][i];
                float2 w = Ws2[i * 32 + l];
                a0 += x * w.x; a1 += x * w.y;
            }
            if (gr < NN) Y2[gr * 32 + l] = make_float2(a0, a1);
        }
    }
}

// edge projection: g_ep = EF @ We. EE is an exact multiple of 32.
__global__ __launch_bounds__(256) void k_ep(
    const float* __restrict__ EF, const float* __restrict__ We)
{
    __shared__ float Ws[D * D];
    __shared__ float Xs[32][D];
    int t = threadIdx.x;
    for (int i = t; i < D * D; i += 256) Ws[i] = We[i];
    size_t row0 = (size_t)blockIdx.x * 32;
    for (int i = t; i < 32 * D; i += 256) {
        int r = i >> 6, c = i & 63;
        Xs[r][c] = EF[(row0 + r) * D + c];
    }
    __syncthreads();
    int l = t & 31, ng = t >> 5;
    const float2* Ws2 = (const float2*)Ws;
    float2* Y2 = (float2*)g_ep;
#pragma unroll
    for (int rr = 0; rr < 4; rr++) {
        int r = rr * 8 + ng;
        float a0 = 0.f, a1 = 0.f;
#pragma unroll
        for (int i = 0; i < D; i++) {
            float x = Xs[r][i];
            float2 w = Ws2[i * 32 + l];
            a0 += x * w.x; a1 += x * w.y;
        }
        Y2[(row0 + r) * 32 + l] = make_float2(a0, a1);
    }
}

// edge_index is int32 (JAX default; int64 in the reference is demoted).
__global__ void k_hist(const int* __restrict__ ei) {
    int e = blockIdx.x * blockDim.x + threadIdx.x;
    if (e < EE) {
        int tgt = ei[EE + e];
        if (tgt >= 0 && tgt < NN) atomicAdd(&g_hist[tgt], 1);
    }
}

// single-block exclusive scan over g_hist -> g_off, g_cur
__global__ __launch_bounds__(1024) void k_scan() {
    __shared__ int sdata[1024];
    __shared__ int s_carry;
    int t = threadIdx.x;
    if (t == 0) s_carry = 0;
    __syncthreads();
    for (int base = 0; base < NN; base += 1024) {
        int idx = base + t;
        int v = (idx < NN) ? g_hist[idx] : 0;
        sdata[t] = v;
        __syncthreads();
        for (int ofs = 1; ofs < 1024; ofs <<= 1) {
            int add = (t >= ofs) ? sdata[t - ofs] : 0;
            __syncthreads();
            sdata[t] += add;
            __syncthreads();
        }
        int excl = sdata[t] - v;
        if (idx < NN) {
            g_off[idx] = s_carry + excl;
            g_cur[idx] = s_carry + excl;
        }
        __syncthreads();
        if (t == 1023) s_carry += sdata[1023];
        __syncthreads();
    }
    if (t == 0) g_off[NN] = s_carry;
}

__global__ void k_scatter(const int* __restrict__ ei) {
    int e = blockIdx.x * blockDim.x + threadIdx.x;
    if (e < EE) {
        int tgt = ei[EE + e];
        if (tgt >= 0 && tgt < NN) {
            int pos = atomicAdd(&g_cur[tgt], 1);
            if (pos >= 0 && pos < EE) g_perm[pos] = e;
        }
    }
}

// one warp per node: softmax-attention aggregation + Wo + residual
#define EBUF 96
__global__ __launch_bounds__(256) void k_attn(
    const float* __restrict__ X, const int* __restrict__ ei,
    const float* __restrict__ Wo)
{
    __shared__ float Wos[D * D];
    __shared__ int   eb[8][EBUF];
    __shared__ float aggs[8][D];
    int t = threadIdx.x;
    for (int i = t; i < D * D; i += 256) Wos[i] = Wo[i];
    __syncthreads();

    int w = t >> 5, l = t & 31;
    int node = blockIdx.x * 8 + w;
    if (node >= NN) return;

    int o0 = g_off[node];
    int deg = g_off[node + 1] - o0;
    bool buf = (deg <= EBUF);
    if (buf) {
        for (int j = l; j < deg; j += 32) eb[w][j] = g_perm[o0 + j];
        __syncwarp();
        if (l == 0) {  // deterministic accumulation order
            for (int a = 1; a < deg; a++) {
                int key = eb[w][a]; int b = a - 1;
                while (b >= 0 && eb[w][b] > key) { eb[w][b + 1] = eb[w][b]; b--; }
                eb[w][b + 1] = key;
            }
        }
        __syncwarp();
    }

    const float2* q2  = (const float2*)g_q;
    const float2* k2  = (const float2*)g_k;
    const float2* v2  = (const float2*)g_v;
    const float2* ep2 = (const float2*)g_ep;

    float2 q = q2[node * 32 + l];
    float a0 = 0.f, a1 = 0.f, den = 0.f;
    for (int j = 0; j < deg; j++) {
        int e = buf ? eb[w][j] : g_perm[o0 + j];
        int s = ei[e];
        float2 epv = ep2[(size_t)e * 32 + l];
        float2 kv  = k2[s * 32 + l];
        float2 vv  = v2[s * 32 + l];
        float p = q.x * (kv.x + epv.x) + q.y * (kv.y + epv.y);
        p += __shfl_xor_sync(0xffffffffu, p, 1);
        p += __shfl_xor_sync(0xffffffffu, p, 2);
        p += __shfl_xor_sync(0xffffffffu, p, 4);   // 16-dim head dot done
        float ex = __expf(p * 0.25f);              // bounded scores: no max-shift
        den += ex;
        a0 += ex * (vv.x + epv.x);
        a1 += ex * (vv.y + epv.y);
    }
    float inv = (deg > 0) ? (1.0f / den) : 0.f;
    aggs[w][2 * l]     = a0 * inv;
    aggs[w][2 * l + 1] = a1 * inv;
    __syncwarp();

    float2 xr = ((const float2*)X)[node * 32 + l];
    float n0 = xr.x, n1 = xr.y;
    const float2* Wos2 = (const float2*)Wos;
#pragma unroll
    for (int i = 0; i < D; i++) {
        float a = aggs[w][i];
        float2 wv = Wos2[i * 32 + l];
        n0 += a * wv.x; n1 += a * wv.y;
    }
    ((float2*)g_nn)[node * 32 + l] = make_float2(n0, n1);
}

// edge classifier as tiled GEMM: tile = 64 edges x 64 hidden, K = 192 in 3
// chunks of 64 (nn[src] | nn[tgt] | ef). 4x4 micro-tile per thread.
// A tile stored TRANSPOSED [kk][m] with stride 68 -> conflict-free float4
// reads along m; staging writes hit 32 distinct banks (row = lane).
#define ATS 68
__global__ __launch_bounds__(256) void k_cls(
    const float* __restrict__ EF, const int* __restrict__ ei,
    const float* __restrict__ W1, const float* __restrict__ b1,
    const float* __restrict__ W2, const float* __restrict__ b2,
    float* __restrict__ out)
{
    __shared__ float At[64 * ATS];  // transposed A tile; reused as reduction buf
    __shared__ float Bs[64 * 64];   // W1 chunk
    __shared__ int   es[64], et[64];
    int t = threadIdx.x;
    int e0 = blockIdx.x * 64;
    if (t < 64) {
        es[t] = ei[e0 + t];
        et[t] = ei[EE + e0 + t];
    }
    int cg = t & 15, rg = t >> 4;     // col group 0..15, row group 0..15

    float acc[4][4];
#pragma unroll
    for (int i = 0; i < 4; i++)
#pragma unroll
        for (int j = 0; j < 4; j++) acc[i][j] = 0.f;

    for (int ck = 0; ck < 3; ck++) {
        __syncthreads();
        // stage A chunk transposed: each thread loads one float4 of row `row`
        // (row = lane -> conflict-free scattered STS into At[kk][row])
        for (int idx = t; idx < 64 * 16; idx += 256) {
            int row = idx & 63, q = idx >> 6;
            const float4* src;
            if (ck == 0)      src = (const float4*)(g_nn + (size_t)es[row] * 64);
            else if (ck == 1) src = (const float4*)(g_nn + (size_t)et[row] * 64);
            else              src = (const float4*)(EF + (size_t)(e0 + row) * 64);
            float4 vv = src[q];
            At[(4 * q + 0) * ATS + row] = vv.x;
            At[(4 * q + 1) * ATS + row] = vv.y;
            At[(4 * q + 2) * ATS + row] = vv.z;
            At[(4 * q + 3) * ATS + row] = vv.w;
        }
        // stage B chunk: W1 rows [ck*64, ck*64+64)
        for (int idx = t; idx < 64 * 16; idx += 256)
            ((float4*)Bs)[idx] = ((const float4*)(W1 + ck * 64 * 64))[idx];
        __syncthreads();

#pragma unroll 16
        for (int kk = 0; kk < 64; kk++) {
            float4 b = ((const float4*)Bs)[kk * 16 + cg];
            float4 a = *(const float4*)&At[kk * ATS + rg * 4];
            acc[0][0] += a.x * b.x; acc[0][1] += a.x * b.y;
            acc[0][2] += a.x * b.z; acc[0][3] += a.x * b.w;
            acc[1][0] += a.y * b.x; acc[1][1] += a.y * b.y;
            acc[1][2] += a.y * b.z; acc[1][3] += a.y * b.w;
            acc[2][0] += a.z * b.x; acc[2][1] += a.z * b.y;
            acc[2][2] += a.z * b.z; acc[2][3] += a.z * b.w;
            acc[3][0] += a.w * b.x; acc[3][1] += a.w * b.y;
            acc[3][2] += a.w * b.z; acc[3][3] += a.w * b.w;
        }
    }

    // epilogue: bias + exact gelu + x W2[64,2], partial per col-group
    float4 b1v = ((const float4*)b1)[cg];
    float bb1[4] = {b1v.x, b1v.y, b1v.z, b1v.w};
    float o0[4] = {0.f, 0.f, 0.f, 0.f};
    float o1[4] = {0.f, 0.f, 0.f, 0.f};
#pragma unroll
    for (int j = 0; j < 4; j++) {
        float2 w2v = ((const float2*)W2)[cg * 4 + j];
#pragma unroll
        for (int i = 0; i < 4; i++) {
            float h = acc[i][j] + bb1[j];
            h = 0.5f * h * (1.f + erff(h * 0.70710678118654752440f));
            o0[i] += h * w2v.x;
            o1[i] += h * w2v.y;
        }
    }
    __syncthreads();             // done reading At in compute loop
    // reduction buffer (aliases At): [cg][row*2+k], stride 130 vs conflicts
#pragma unroll
    for (int i = 0; i < 4; i++) {
        int row = rg * 4 + i;
        At[cg * 130 + row * 2 + 0] = o0[i];
        At[cg * 130 + row * 2 + 1] = o1[i];
    }
    __syncthreads();
    if (t < 128) {
        int row = t >> 1, k = t & 1;
        float s = 0.f;
#pragma unroll
        for (int c = 0; c < 16; c++) s += At[c * 130 + row * 2 + k];
        out[(size_t)(e0 + row) * 2 + k] = s + b2[k];
    }
}

// ---------------- launcher: kernel launches ONLY -----------------------------

extern "C" void kernel_launch(void* const* d_in, const int* in_sizes, int n_in,
                              void* d_out, int out_size)
{
    const float* X  = (const float*)d_in[0];
    const float* EF = (const float*)d_in[1];
    const int*   ei = (const int*)d_in[2];     // int32 edge_index (JAX default)
    const float* Wq = (const float*)d_in[3];
    const float* Wk = (const float*)d_in[4];
    const float* Wv = (const float*)d_in[5];
    const float* We = (const float*)d_in[6];
    const float* Wo = (const float*)d_in[7];
    const float* W1 = (const float*)d_in[8];
    const float* b1 = (const float*)d_in[9];
    const float* W2 = (const float*)d_in[10];
    const float* b2 = (const float*)d_in[11];
    float* out = (float*)d_out;

    // projections
    k_qkv<<<(NN + 31) / 32, 256>>>(X, Wq, Wk, Wv);
    k_ep<<<EE / 32, 256>>>(EF, We);

    // CSR by target
    k_zero_hist<<<(NN + 255) / 256, 256>>>();
    k_hist<<<(EE + 255) / 256, 256>>>(ei);
    k_scan<<<1, 1024>>>();
    k_scatter<<<(EE + 255) / 256, 256>>>(ei);

    // attention aggregation + residual
    k_attn<<<(NN + 7) / 8, 256>>>(X, ei, Wo);

    // edge classifier (tiled GEMM + fused gelu/W2)
    k_cls<<<EE / 64, 256>>>(EF, ei, W1, b1, W2, b2, out);
}

// round 14
// speedup vs baseline: 1.0848x; 1.0848x over previous
#include <cuda_runtime.h>
#include <math.h>

#define NN 50000
#define EE 800000
#define D  64

typedef unsigned long long ull;

// packed f32x2 helpers (sm_100+)
#define FMA2(acc, a, b) \
    asm("fma.rn.f32x2 %0, %1, %2, %0;" : "+l"(acc) : "l"(a), "l"(b))
#define SPLAT2(dst, s) \
    asm("mov.b64 %0, {%1, %1};" : "=l"(dst) : "f"(s))
#define UNPACK2(lo, hi, v) \
    asm("mov.b64 {%0, %1}, %2;" : "=f"(lo), "=f"(hi) : "l"(v))

// ---------------- scratch (device globals; no allocations allowed) ----------
__device__ float g_q[NN * D];
__device__ float g_k[NN * D];
__device__ float g_v[NN * D];
__device__ float g_ep[(size_t)EE * D];   // 204.8 MB
__device__ float g_nn[NN * D];
__device__ int   g_hist[NN];
__device__ int   g_off[NN + 1];
__device__ int   g_cur[NN];
__device__ int   g_perm[EE];

// ---------------- kernels ---------------------------------------------------

__global__ void k_zero_hist() {
    int i = blockIdx.x * blockDim.x + threadIdx.x;
    if (i < NN) g_hist[i] = 0;
}

// q,k,v projections fused: one X-tile load, three weights. 32 rows per block.
__global__ __launch_bounds__(256) void k_qkv(
    const float* __restrict__ X,
    const float* __restrict__ Wq, const float* __restrict__ Wk,
    const float* __restrict__ Wv)
{
    __shared__ float Ws[D * D];
    __shared__ float Xs[32][D];
    int t = threadIdx.x;
    int row0 = blockIdx.x * 32;
    for (int i = t; i < 32 * D; i += 256) {
        int r = i >> 6, c = i & 63;
        int gr = row0 + r;
        Xs[r][c] = (gr < NN) ? X[gr * D + c] : 0.f;
    }
    const float* Wlist[3] = {Wq, Wk, Wv};
    float2* Olist[3] = {(float2*)g_q, (float2*)g_k, (float2*)g_v};
    int l = t & 31, ng = t >> 5;
    for (int m = 0; m < 3; m++) {
        __syncthreads();
        for (int i = t; i < D * D; i += 256) Ws[i] = Wlist[m][i];
        __syncthreads();
        const float2* Ws2 = (const float2*)Ws;
        float2* Y2 = Olist[m];
#pragma unroll
        for (int rr = 0; rr < 4; rr++) {
            int r = rr * 8 + ng;
            int gr = row0 + r;
            float a0 = 0.f, a1 = 0.f;
#pragma unroll
            for (int i = 0; i < D; i++) {
                float x = Xs[r][i];
                float2 w = Ws2[i * 32 + l];
                a0 += x * w.x; a1 += x * w.y;
            }
            if (gr < NN) Y2[gr * 32 + l] = make_float2(a0, a1);
        }
    }
}

// edge projection: g_ep = EF @ We. EE is an exact multiple of 32.
__global__ __launch_bounds__(256) void k_ep(
    const float* __restrict__ EF, const float* __restrict__ We)
{
    __shared__ float Ws[D * D];
    __shared__ float Xs[32][D];
    int t = threadIdx.x;
    for (int i = t; i < D * D; i += 256) Ws[i] = We[i];
    size_t row0 = (size_t)blockIdx.x * 32;
    for (int i = t; i < 32 * D; i += 256) {
        int r = i >> 6, c = i & 63;
        Xs[r][c] = EF[(row0 + r) * D + c];
    }
    __syncthreads();
    int l = t & 31, ng = t >> 5;
    const float2* Ws2 = (const float2*)Ws;
    float2* Y2 = (float2*)g_ep;
#pragma unroll
    for (int rr = 0; rr < 4; rr++) {
        int r = rr * 8 + ng;
        float a0 = 0.f, a1 = 0.f;
#pragma unroll
        for (int i = 0; i < D; i++) {
            float x = Xs[r][i];
            float2 w = Ws2[i * 32 + l];
            a0 += x * w.x; a1 += x * w.y;
        }
        Y2[(row0 + r) * 32 + l] = make_float2(a0, a1);
    }
}

// edge_index is int32 (JAX default; int64 in the reference is demoted).
__global__ void k_hist(const int* __restrict__ ei) {
    int e = blockIdx.x * blockDim.x + threadIdx.x;
    if (e < EE) {
        int tgt = ei[EE + e];
        if (tgt >= 0 && tgt < NN) atomicAdd(&g_hist[tgt], 1);
    }
}

// single-block exclusive scan over g_hist -> g_off, g_cur
__global__ __launch_bounds__(1024) void k_scan() {
    __shared__ int sdata[1024];
    __shared__ int s_carry;
    int t = threadIdx.x;
    if (t == 0) s_carry = 0;
    __syncthreads();
    for (int base = 0; base < NN; base += 1024) {
        int idx = base + t;
        int v = (idx < NN) ? g_hist[idx] : 0;
        sdata[t] = v;
        __syncthreads();
        for (int ofs = 1; ofs < 1024; ofs <<= 1) {
            int add = (t >= ofs) ? sdata[t - ofs] : 0;
            __syncthreads();
            sdata[t] += add;
            __syncthreads();
        }
        int excl = sdata[t] - v;
        if (idx < NN) {
            g_off[idx] = s_carry + excl;
            g_cur[idx] = s_carry + excl;
        }
        __syncthreads();
        if (t == 1023) s_carry += sdata[1023];
        __syncthreads();
    }
    if (t == 0) g_off[NN] = s_carry;
}

__global__ void k_scatter(const int* __restrict__ ei) {
    int e = blockIdx.x * blockDim.x + threadIdx.x;
    if (e < EE) {
        int tgt = ei[EE + e];
        if (tgt >= 0 && tgt < NN) {
            int pos = atomicAdd(&g_cur[tgt], 1);
            if (pos >= 0 && pos < EE) g_perm[pos] = e;
        }
    }
}

// one warp per node: softmax-attention aggregation + Wo + residual
#define EBUF 96
__global__ __launch_bounds__(256) void k_attn(
    const float* __restrict__ X, const int* __restrict__ ei,
    const float* __restrict__ Wo)
{
    __shared__ float Wos[D * D];
    __shared__ int   eb[8][EBUF];
    __shared__ float aggs[8][D];
    int t = threadIdx.x;
    for (int i = t; i < D * D; i += 256) Wos[i] = Wo[i];
    __syncthreads();

    int w = t >> 5, l = t & 31;
    int node = blockIdx.x * 8 + w;
    if (node >= NN) return;

    int o0 = g_off[node];
    int deg = g_off[node + 1] - o0;
    bool buf = (deg <= EBUF);
    if (buf) {
        for (int j = l; j < deg; j += 32) eb[w][j] = g_perm[o0 + j];
        __syncwarp();
        if (l == 0) {  // deterministic accumulation order
            for (int a = 1; a < deg; a++) {
                int key = eb[w][a]; int b = a - 1;
                while (b >= 0 && eb[w][b] > key) { eb[w][b + 1] = eb[w][b]; b--; }
                eb[w][b + 1] = key;
            }
        }
        __syncwarp();
    }

    const float2* q2  = (const float2*)g_q;
    const float2* k2  = (const float2*)g_k;
    const float2* v2  = (const float2*)g_v;
    const float2* ep2 = (const float2*)g_ep;

    float2 q = q2[node * 32 + l];
    float a0 = 0.f, a1 = 0.f, den = 0.f;
    for (int j = 0; j < deg; j++) {
        int e = buf ? eb[w][j] : g_perm[o0 + j];
        int s = ei[e];
        float2 epv = ep2[(size_t)e * 32 + l];
        float2 kv  = k2[s * 32 + l];
        float2 vv  = v2[s * 32 + l];
        float p = q.x * (kv.x + epv.x) + q.y * (kv.y + epv.y);
        p += __shfl_xor_sync(0xffffffffu, p, 1);
        p += __shfl_xor_sync(0xffffffffu, p, 2);
        p += __shfl_xor_sync(0xffffffffu, p, 4);   // 16-dim head dot done
        float ex = __expf(p * 0.25f);              // bounded scores: no max-shift
        den += ex;
        a0 += ex * (vv.x + epv.x);
        a1 += ex * (vv.y + epv.y);
    }
    float inv = (deg > 0) ? (1.0f / den) : 0.f;
    aggs[w][2 * l]     = a0 * inv;
    aggs[w][2 * l + 1] = a1 * inv;
    __syncwarp();

    float2 xr = ((const float2*)X)[node * 32 + l];
    float n0 = xr.x, n1 = xr.y;
    const float2* Wos2 = (const float2*)Wos;
#pragma unroll
    for (int i = 0; i < D; i++) {
        float a = aggs[w][i];
        float2 wv = Wos2[i * 32 + l];
        n0 += a * wv.x; n1 += a * wv.y;
    }
    ((float2*)g_nn)[node * 32 + l] = make_float2(n0, n1);
}

// edge classifier as tiled GEMM: tile = 64 edges x 64 hidden, K = 192 in 3
// chunks of 64 (nn[src] | nn[tgt] | ef). 4x4 micro-tile per thread.
// R6 row-major staging (A reads are 2-address broadcasts, conflict-free).
// Inner loop uses packed fma.rn.f32x2: 8 FFMA2 instead of 16 FFMA per kk.
__global__ __launch_bounds__(256) void k_cls(
    const float* __restrict__ EF, const int* __restrict__ ei,
    const float* __restrict__ W1, const float* __restrict__ b1,
    const float* __restrict__ W2, const float* __restrict__ b2,
    float* __restrict__ out)
{
    __shared__ float As[64 * 64];   // A tile; reused as reduction buffer
    __shared__ float Bs[64 * 64];   // W1 chunk
    __shared__ int   es[64], et[64];
    int t = threadIdx.x;
    int e0 = blockIdx.x * 64;
    if (t < 64) {
        es[t] = ei[e0 + t];
        et[t] = ei[EE + e0 + t];
    }
    int cg = t & 15, rg = t >> 4;     // col group 0..15, row group 0..15

    ull acc2[4][2];                    // [row][colpair], packed f32x2
    {
        float z = 0.f;
        ull zz; SPLAT2(zz, z);
#pragma unroll
        for (int i = 0; i < 4; i++) { acc2[i][0] = zz; acc2[i][1] = zz; }
    }

    for (int ck = 0; ck < 3; ck++) {
        __syncthreads();
        // stage A chunk: 64 rows x 64 floats, gathered (float4 STS)
        for (int idx = t; idx < 64 * 16; idx += 256) {
            int row = idx >> 4, q = idx & 15;
            const float4* src;
            if (ck == 0)      src = (const float4*)(g_nn + (size_t)es[row] * 64);
            else if (ck == 1) src = (const float4*)(g_nn + (size_t)et[row] * 64);
            else              src = (const float4*)(EF + (size_t)(e0 + row) * 64);
            ((float4*)As)[row * 16 + q] = src[q];
        }
        // stage B chunk: W1 rows [ck*64, ck*64+64)
        for (int idx = t; idx < 64 * 16; idx += 256)
            ((float4*)Bs)[idx] = ((const float4*)(W1 + ck * 64 * 64))[idx];
        __syncthreads();

        const ull* Bs2 = (const ull*)Bs;
#pragma unroll 16
        for (int kk = 0; kk < 64; kk++) {
            ull b0 = Bs2[kk * 32 + cg * 2];      // cols 4cg,4cg+1
            ull b1 = Bs2[kk * 32 + cg * 2 + 1];  // cols 4cg+2,4cg+3
#pragma unroll
            for (int i = 0; i < 4; i++) {
                float a = As[(rg * 4 + i) * 64 + kk];  // broadcast
                ull pa; SPLAT2(pa, a);
                FMA2(acc2[i][0], pa, b0);
                FMA2(acc2[i][1], pa, b1);
            }
        }
    }

    // unpack packed accumulators -> acc[i][j] (same values as scalar path)
    float acc[4][4];
#pragma unroll
    for (int i = 0; i < 4; i++) {
        UNPACK2(acc[i][0], acc[i][1], acc2[i][0]);
        UNPACK2(acc[i][2], acc[i][3], acc2[i][1]);
    }

    // epilogue: bias + exact gelu + x W2[64,2], partial per col-group
    float4 b1v = ((const float4*)b1)[cg];
    float bb1[4] = {b1v.x, b1v.y, b1v.z, b1v.w};
    float o0[4] = {0.f, 0.f, 0.f, 0.f};
    float o1[4] = {0.f, 0.f, 0.f, 0.f};
#pragma unroll
    for (int j = 0; j < 4; j++) {
        float2 w2v = ((const float2*)W2)[cg * 4 + j];
#pragma unroll
        for (int i = 0; i < 4; i++) {
            float h = acc[i][j] + bb1[j];
            h = 0.5f * h * (1.f + erff(h * 0.70710678118654752440f));
            o0[i] += h * w2v.x;
            o1[i] += h * w2v.y;
        }
    }
    __syncthreads();             // done reading As in compute loop
    // reduction buffer: [cg][row*2+k], stride 130 to dodge bank conflicts
#pragma unroll
    for (int i = 0; i < 4; i++) {
        int row = rg * 4 + i;
        As[cg * 130 + row * 2 + 0] = o0[i];
        As[cg * 130 + row * 2 + 1] = o1[i];
    }
    __syncthreads();
    if (t < 128) {
        int row = t >> 1, k = t & 1;
        float s = 0.f;
#pragma unroll
        for (int c = 0; c < 16; c++) s += As[c * 130 + row * 2 + k];
        out[(size_t)(e0 + row) * 2 + k] = s + b2[k];
    }
}

// ---------------- launcher: kernel launches ONLY -----------------------------

extern "C" void kernel_launch(void* const* d_in, const int* in_sizes, int n_in,
                              void* d_out, int out_size)
{
    const float* X  = (const float*)d_in[0];
    const float* EF = (const float*)d_in[1];
    const int*   ei = (const int*)d_in[2];     // int32 edge_index (JAX default)
    const float* Wq = (const float*)d_in[3];
    const float* Wk = (const float*)d_in[4];
    const float* Wv = (const float*)d_in[5];
    const float* We = (const float*)d_in[6];
    const float* Wo = (const float*)d_in[7];
    const float* W1 = (const float*)d_in[8];
    const float* b1 = (const float*)d_in[9];
    const float* W2 = (const float*)d_in[10];
    const float* b2 = (const float*)d_in[11];
    float* out = (float*)d_out;

    // projections
    k_qkv<<<(NN + 31) / 32, 256>>>(X, Wq, Wk, Wv);
    k_ep<<<EE / 32, 256>>>(EF, We);

    // CSR by target
    k_zero_hist<<<(NN + 255) / 256, 256>>>();
    k_hist<<<(EE + 255) / 256, 256>>>(ei);
    k_scan<<<1, 1024>>>();
    k_scatter<<<(EE + 255) / 256, 256>>>(ei);

    // attention aggregation + residual
    k_attn<<<(NN + 7) / 8, 256>>>(X, ei, Wo);

    // edge classifier (tiled GEMM + fused gelu/W2, packed f32x2 FMAs)
    k_cls<<<EE / 64, 256>>>(EF, ei, W1, b1, W2, b2, out);
}